// round 7
// baseline (speedup 1.0000x reference)
#include <cuda_runtime.h>
#include <cstdint>
#include <math.h>

#define NN    10000
#define IND   512
#define D1    512      // HEADS*HID
#define HEADS 8
#define HID   64
#define D2    64
#define ODIM  5000
#define NE    160000
#define ET    170000   // NE + NN self loops
#define NEG   0.2f

// ---------------- scratch (static device globals; no allocation) ------------
__device__ float    g_xl1[(size_t)NN * D1];
__device__ float    g_xr1[(size_t)NN * D1];
__device__ float    g_h1 [(size_t)NN * D1];
__device__ float    g_xl2[(size_t)NN * D2];
__device__ float    g_xr2[(size_t)NN * D2];
__device__ float    g_h2 [(size_t)NN * D2];
__device__ int      g_deg[NN];
__device__ int      g_off[NN + 1];
__device__ int      g_cur[NN];
__device__ int      g_perm[ET];
__device__ int      g_is64;

// ---------------- helpers ---------------------------------------------------
__device__ __forceinline__ int eidx(const void* ei, int i) {
    return g_is64 ? (int)((const long long*)ei)[i] : ((const int*)ei)[i];
}
__device__ __forceinline__ int esrc(const void* ei, int w) {
    return (w < NE) ? eidx(ei, w) : (w - NE);
}
__device__ __forceinline__ int edst(const void* ei, int w) {
    return (w < NE) ? eidx(ei, NE + w) : (w - NE);
}
__device__ __forceinline__ float lrelu(float v) { return v > 0.f ? v : NEG * v; }
__device__ __forceinline__ uint32_t f2tf32(float f) {
    uint32_t r; asm("cvt.rna.tf32.f32 %0, %1;" : "=r"(r) : "f"(f)); return r;
}

// ---------------- tf32 mma.sync GEMM (software pipelined) --------------------
#define BKC 32
#define STR 36

__device__ __forceinline__ void mma16n8k8(float* c, const uint32_t* a, const uint32_t* b) {
    asm volatile("mma.sync.aligned.m16n8k8.row.col.f32.tf32.tf32.f32 "
        "{%0,%1,%2,%3}, {%4,%5,%6,%7}, {%8,%9}, {%0,%1,%2,%3};"
        : "+f"(c[0]), "+f"(c[1]), "+f"(c[2]), "+f"(c[3])
        : "r"(a[0]), "r"(a[1]), "r"(a[2]), "r"(a[3]), "r"(b[0]), "r"(b[1]));
}

__global__ __launch_bounds__(256) void tc_gemm(
    const float* __restrict__ A,
    const float* __restrict__ Wa, const float* __restrict__ Wb,
    const float* __restrict__ ba, const float* __restrict__ bb,
    float* __restrict__ Ca, float* __restrict__ Cb,
    int split, int M, int Nc, int K)
{
    __shared__ uint32_t As[128 * STR];
    __shared__ uint32_t Bs[128 * STR];

    int tid = threadIdx.x, wid = tid >> 5, lane = tid & 31;
    int g = lane >> 2, q = lane & 3;
    int wm = wid >> 2, wn = wid & 3;
    int rowBase = blockIdx.y * 128, colBase = blockIdx.x * 128;

    int srow = tid >> 1;
    int scol = (tid & 1) * 16;
    int garow = rowBase + srow;
    int gbrow = colBase + srow;
    const float* agp = (garow < M) ? A + (size_t)garow * K + scol : nullptr;
    const float* bgp = nullptr;
    if (gbrow < Nc)
        bgp = (gbrow < split) ? Wa + (size_t)gbrow * K + scol
                              : Wb + (size_t)(gbrow - split) * K + scol;

    float acc[4][4][4];
    #pragma unroll
    for (int i = 0; i < 4; i++)
        #pragma unroll
        for (int j = 0; j < 4; j++)
            #pragma unroll
            for (int r = 0; r < 4; r++) acc[i][j][r] = 0.f;

    int ncK = K / BKC;
    float4 ra[4], rb[4];
    #pragma unroll
    for (int j = 0; j < 4; j++) {
        ra[j] = agp ? *(const float4*)(agp + j * 4) : make_float4(0.f, 0.f, 0.f, 0.f);
        rb[j] = bgp ? *(const float4*)(bgp + j * 4) : make_float4(0.f, 0.f, 0.f, 0.f);
    }

    for (int c = 0; c < ncK; c++) {
        #pragma unroll
        for (int j = 0; j < 4; j++) {
            uint32_t* ad = &As[srow * STR + scol + j * 4];
            uint32_t* bd = &Bs[srow * STR + scol + j * 4];
            ad[0] = f2tf32(ra[j].x); ad[1] = f2tf32(ra[j].y);
            ad[2] = f2tf32(ra[j].z); ad[3] = f2tf32(ra[j].w);
            bd[0] = f2tf32(rb[j].x); bd[1] = f2tf32(rb[j].y);
            bd[2] = f2tf32(rb[j].z); bd[3] = f2tf32(rb[j].w);
        }
        __syncthreads();

        if (c + 1 < ncK) {
            int k0 = (c + 1) * BKC;
            #pragma unroll
            for (int j = 0; j < 4; j++) {
                ra[j] = agp ? *(const float4*)(agp + k0 + j * 4)
                            : make_float4(0.f, 0.f, 0.f, 0.f);
                rb[j] = bgp ? *(const float4*)(bgp + k0 + j * 4)
                            : make_float4(0.f, 0.f, 0.f, 0.f);
            }
        }

        #pragma unroll
        for (int kk = 0; kk < BKC; kk += 8) {
            uint32_t afr[4][4], bfr[4][2];
            #pragma unroll
            for (int i = 0; i < 4; i++) {
                int r = wm * 64 + i * 16 + g;
                afr[i][0] = As[(r    ) * STR + kk + q    ];
                afr[i][1] = As[(r + 8) * STR + kk + q    ];
                afr[i][2] = As[(r    ) * STR + kk + q + 4];
                afr[i][3] = As[(r + 8) * STR + kk + q + 4];
            }
            #pragma unroll
            for (int j = 0; j < 4; j++) {
                int n = wn * 32 + j * 8 + g;
                bfr[j][0] = Bs[n * STR + kk + q    ];
                bfr[j][1] = Bs[n * STR + kk + q + 4];
            }
            #pragma unroll
            for (int i = 0; i < 4; i++)
                #pragma unroll
                for (int j = 0; j < 4; j++)
                    mma16n8k8(acc[i][j], afr[i], bfr[j]);
        }
        __syncthreads();
    }

    #pragma unroll
    for (int i = 0; i < 4; i++) {
        int r0 = rowBase + wm * 64 + i * 16 + g;
        #pragma unroll
        for (int j = 0; j < 4; j++) {
            int c = colBase + wn * 32 + j * 8 + q * 2;
            if (c >= Nc) continue;
            float bv0, bv1;
            float* dst0; float* dst1;
            if (c < split) {
                bv0 = ba[c]; bv1 = ba[c + 1];
                dst0 = Ca + (size_t)r0 * split + c;
                dst1 = Ca + (size_t)(r0 + 8) * split + c;
            } else {
                int cc = c - split; int w2 = Nc - split;
                bv0 = bb[cc]; bv1 = bb[cc + 1];
                dst0 = Cb + (size_t)r0 * w2 + cc;
                dst1 = Cb + (size_t)(r0 + 8) * w2 + cc;
            }
            if (r0 < M)
                *(float2*)dst0 = make_float2(acc[i][j][0] + bv0, acc[i][j][1] + bv1);
            if (r0 + 8 < M)
                *(float2*)dst1 = make_float2(acc[i][j][2] + bv0, acc[i][j][3] + bv1);
        }
    }
}

// ---------------- int64/int32 edge-index detection --------------------------
__global__ void detect_kernel(const void* ei) {
    const long long* p = (const long long*)ei;
    int ok = 1;
    for (int i = 0; i < 64; i++) {
        long long v = p[i];
        if (v < 0 || v >= NN) { ok = 0; break; }
    }
    g_is64 = ok;
}

__global__ void init_kernel() {
    int i = blockIdx.x * blockDim.x + threadIdx.x;
    if (i < NN) g_deg[i] = 0;
    if (i == 0) g_off[NN] = ET;
}

// ---------------- CSR build -------------------------------------------------
__global__ void deg_kernel(const void* ei) {
    int w = blockIdx.x * blockDim.x + threadIdx.x;
    if (w >= ET) return;
    atomicAdd(&g_deg[edst(ei, w)], 1);
}

// hierarchical scan: 10 elems/thread, warp shfl scan, 32-partial scan
__global__ __launch_bounds__(1024) void scan_kernel() {
    __shared__ int wsum[32];
    int t = threadIdx.x, lane = t & 31, wid = t >> 5;
    const int CH = 10;                       // 1024*10 >= NN
    int base = t * CH;
    int loc[CH];
    int s = 0;
    #pragma unroll
    for (int k = 0; k < CH; k++) {
        int i = base + k;
        int v = (i < NN) ? g_deg[i] : 0;
        loc[k] = s;
        s += v;
    }
    int inc = s;
    #pragma unroll
    for (int o = 1; o < 32; o <<= 1) {
        int n = __shfl_up_sync(0xffffffffu, inc, o);
        if (lane >= o) inc += n;
    }
    if (lane == 31) wsum[wid] = inc;
    __syncthreads();
    if (wid == 0) {
        int w = wsum[lane];
        #pragma unroll
        for (int o = 1; o < 32; o <<= 1) {
            int n = __shfl_up_sync(0xffffffffu, w, o);
            if (lane >= o) w += n;
        }
        wsum[lane] = w;
    }
    __syncthreads();
    int thbase = inc - s + (wid ? wsum[wid - 1] : 0);
    #pragma unroll
    for (int k = 0; k < CH; k++) {
        int i = base + k;
        if (i < NN) {
            int e = thbase + loc[k];
            g_off[i] = e;
            g_cur[i] = e;
        }
    }
}

__global__ void scatter_kernel(const void* ei) {
    int w = blockIdx.x * blockDim.x + threadIdx.x;
    if (w >= ET) return;
    int pos = atomicAdd(&g_cur[edst(ei, w)], 1);
    g_perm[pos] = w;
}

// ---------------- layer-1 fused: chunked two-pass, PER-HEAD softmax ----------
// Phase A: warps score chunk edges in parallel, producing 8 per-head scores
// per edge (sc[i][h]). Phase B: warp w owns head w — warp-local online
// softmax over its head column. Phase C: warp w aggregates head-w channels.
#define CS1 128
__global__ __launch_bounds__(256) void gat1_fused(const void* ei,
                                                  const float* __restrict__ att,
                                                  const float* __restrict__ bias)
{
    __shared__ float sc[CS1 * 8];
    __shared__ int   sidx[CS1];

    int d = blockIdx.x;
    int t = threadIdx.x, wid = t >> 5, lane = t & 31;

    float xr_r[16], att_r[16];
    #pragma unroll
    for (int j = 0; j < 16; j++) {
        xr_r[j]  = g_xr1[(size_t)d * D1 + lane + j * 32];
        att_r[j] = att[lane + j * 32];
    }
    int c0 = wid * 64 + lane, c1 = c0 + 32;

    int beg = g_off[d], end = g_off[d + 1];
    float m_run = -INFINITY, ssum = 0.f, acc0 = 0.f, acc1 = 0.f;

    for (int ch = beg; ch < end; ch += CS1) {
        int nc = min(CS1, end - ch);
        // ---- phase A: per-head scores, warps stride over edges ----
        for (int i = wid; i < nc; i += 8) {
            int s = esrc(ei, g_perm[ch + i]);
            const float* xs = g_xl1 + (size_t)s * D1 + lane;
            float p[8];
            #pragma unroll
            for (int h = 0; h < 8; h++) {
                float t0 = lrelu(xs[(2 * h    ) * 32] + xr_r[2 * h    ]) * att_r[2 * h    ];
                float t1 = lrelu(xs[(2 * h + 1) * 32] + xr_r[2 * h + 1]) * att_r[2 * h + 1];
                p[h] = t0 + t1;
            }
            #pragma unroll
            for (int o = 16; o; o >>= 1)
                #pragma unroll
                for (int h = 0; h < 8; h++)
                    p[h] += __shfl_xor_sync(0xffffffffu, p[h], o);
            if (lane == 0) {
                sidx[i] = s;
                #pragma unroll
                for (int h = 0; h < 8; h++) sc[i * 8 + h] = p[h];
            }
        }
        __syncthreads();
        // ---- phase B: warp-local per-head online softmax (head = wid) ----
        {
            int i0 = lane, i1 = lane + 32, i2 = lane + 64, i3 = lane + 96;
            float v0 = (i0 < nc) ? sc[i0 * 8 + wid] : -INFINITY;
            float v1 = (i1 < nc) ? sc[i1 * 8 + wid] : -INFINITY;
            float v2 = (i2 < nc) ? sc[i2 * 8 + wid] : -INFINITY;
            float v3 = (i3 < nc) ? sc[i3 * 8 + wid] : -INFINITY;
            float mx = fmaxf(fmaxf(v0, v1), fmaxf(v2, v3));
            #pragma unroll
            for (int o = 16; o; o >>= 1)
                mx = fmaxf(mx, __shfl_xor_sync(0xffffffffu, mx, o));
            float mnew = fmaxf(m_run, mx);
            float e0 = (i0 < nc) ? __expf(v0 - mnew) : 0.f;
            float e1 = (i1 < nc) ? __expf(v1 - mnew) : 0.f;
            float e2 = (i2 < nc) ? __expf(v2 - mnew) : 0.f;
            float e3 = (i3 < nc) ? __expf(v3 - mnew) : 0.f;
            if (i0 < nc) sc[i0 * 8 + wid] = e0;
            if (i1 < nc) sc[i1 * 8 + wid] = e1;
            if (i2 < nc) sc[i2 * 8 + wid] = e2;
            if (i3 < nc) sc[i3 * 8 + wid] = e3;
            float cs = e0 + e1 + e2 + e3;
            #pragma unroll
            for (int o = 16; o; o >>= 1) cs += __shfl_xor_sync(0xffffffffu, cs, o);
            float scale = __expf(m_run - mnew);
            m_run = mnew;
            ssum = ssum * scale + cs;
            acc0 *= scale; acc1 *= scale;
        }
        __syncwarp();
        // ---- phase C: aggregate head-wid channels (rows L1-hot) ----
        for (int i = 0; i < nc; i++) {
            float w = sc[i * 8 + wid];
            const float* xs = g_xl1 + (size_t)sidx[i] * D1;
            acc0 += w * xs[c0];
            acc1 += w * xs[c1];
        }
        __syncthreads();
    }
    float inv = 1.f / ssum;
    g_h1[(size_t)d * D1 + c0] = fmaxf(acc0 * inv + bias[c0], 0.f);
    g_h1[(size_t)d * D1 + c1] = fmaxf(acc1 * inv + bias[c1], 0.f);
}

// ---------------- layer-2 fused: chunked two-pass (warp per dst, 1 head) -----
#define CS2 32
__global__ __launch_bounds__(256) void gat2_fused(const void* ei,
                                                  const float* __restrict__ att,
                                                  const float* __restrict__ bias)
{
    __shared__ float sc[8][CS2];
    __shared__ int   sidx[8][CS2];

    int d = (blockIdx.x * blockDim.x + threadIdx.x) >> 5;
    if (d >= NN) return;
    int wid = (threadIdx.x >> 5) & 7;
    int lane = threadIdx.x & 31;
    int c0 = lane, c1 = lane + 32;

    float xr0 = g_xr2[(size_t)d * D2 + c0];
    float xr1v = g_xr2[(size_t)d * D2 + c1];
    float a0 = att[c0], a1 = att[c1];

    int beg = g_off[d], end = g_off[d + 1];
    float m_run = -INFINITY, ssum = 0.f, acc0 = 0.f, acc1 = 0.f;

    for (int ch = beg; ch < end; ch += CS2) {
        int nc = min(CS2, end - ch);
        for (int i = 0; i < nc; i++) {
            int s = esrc(ei, g_perm[ch + i]);
            float v = lrelu(g_xl2[(size_t)s * D2 + c0] + xr0) * a0
                    + lrelu(g_xl2[(size_t)s * D2 + c1] + xr1v) * a1;
            #pragma unroll
            for (int o = 16; o; o >>= 1) v += __shfl_xor_sync(0xffffffffu, v, o);
            if (lane == 0) { sc[wid][i] = v; sidx[wid][i] = s; }
        }
        __syncwarp();
        float myv = (lane < nc) ? sc[wid][lane] : -INFINITY;
        float mx = myv;
        #pragma unroll
        for (int o = 16; o; o >>= 1)
            mx = fmaxf(mx, __shfl_xor_sync(0xffffffffu, mx, o));
        float mnew = fmaxf(m_run, mx);
        float w = (lane < nc) ? __expf(myv - mnew) : 0.f;
        float cs = w;
        #pragma unroll
        for (int o = 16; o; o >>= 1) cs += __shfl_xor_sync(0xffffffffu, cs, o);
        if (lane < nc) sc[wid][lane] = w;
        __syncwarp();
        float scale = __expf(m_run - mnew);
        m_run = mnew;
        ssum = ssum * scale + cs;
        acc0 *= scale; acc1 *= scale;
        for (int i = 0; i < nc; i++) {
            float wgt = sc[wid][i];
            const float* xs = g_xl2 + (size_t)sidx[wid][i] * D2;
            acc0 += wgt * xs[c0];
            acc1 += wgt * xs[c1];
        }
        __syncwarp();
    }
    float inv = 1.f / ssum;
    g_h2[(size_t)d * D2 + c0] = fmaxf(acc0 * inv + bias[c0], 0.f);
    g_h2[(size_t)d * D2 + c1] = fmaxf(acc1 * inv + bias[c1], 0.f);
}

// ---------------- launch ----------------------------------------------------
extern "C" void kernel_launch(void* const* d_in, const int* in_sizes, int n_in,
                              void* d_out, int out_size)
{
    const float* x    = (const float*)d_in[0];
    const void*  ei   = d_in[1];
    const float* W1l  = (const float*)d_in[2];
    const float* b1l  = (const float*)d_in[3];
    const float* W1r  = (const float*)d_in[4];
    const float* b1r  = (const float*)d_in[5];
    const float* att1 = (const float*)d_in[6];
    const float* bias1= (const float*)d_in[7];
    const float* W2l  = (const float*)d_in[8];
    const float* b2l  = (const float*)d_in[9];
    const float* W2r  = (const float*)d_in[10];
    const float* b2r  = (const float*)d_in[11];
    const float* att2 = (const float*)d_in[12];
    const float* bias2= (const float*)d_in[13];
    const float* fcw  = (const float*)d_in[14];
    const float* fcb  = (const float*)d_in[15];
    float* out = (float*)d_out;

    void *p_xl1, *p_xr1, *p_h1, *p_xl2, *p_xr2, *p_h2;
    cudaGetSymbolAddress(&p_xl1, g_xl1);
    cudaGetSymbolAddress(&p_xr1, g_xr1);
    cudaGetSymbolAddress(&p_h1,  g_h1);
    cudaGetSymbolAddress(&p_xl2, g_xl2);
    cudaGetSymbolAddress(&p_xr2, g_xr2);
    cudaGetSymbolAddress(&p_h2,  g_h2);

    detect_kernel<<<1, 1>>>(ei);
    init_kernel<<<(NN + 255) / 256, 256>>>();

    deg_kernel<<<(ET + 255) / 256, 256>>>(ei);
    scan_kernel<<<1, 1024>>>();
    scatter_kernel<<<(ET + 255) / 256, 256>>>(ei);

    // layer-1 transform: fused [10000,512] x [1024,512]^T -> xl1 | xr1
    {
        dim3 g(1024 / 128, (NN + 127) / 128);
        tc_gemm<<<g, 256>>>(x, W1l, W1r, b1l, b1r,
                            (float*)p_xl1, (float*)p_xr1, D1, NN, 1024, IND);
    }

    gat1_fused<<<NN, 256>>>(ei, att1, bias1);

    // layer-2 transform: fused [10000,512] x [128,512]^T -> xl2 | xr2
    {
        dim3 g(1, (NN + 127) / 128);
        tc_gemm<<<g, 256>>>((const float*)p_h1, W2l, W2r, b2l, b2r,
                            (float*)p_xl2, (float*)p_xr2, D2, NN, 128, D1);
    }

    gat2_fused<<<(NN * 32 + 255) / 256, 256>>>(ei, att2, bias2);

    // FC: [10000,64] x [5000,64]^T -> out
    {
        dim3 g((ODIM + 127) / 128, (NN + 127) / 128);
        tc_gemm<<<g, 256>>>((const float*)p_h2, fcw, fcw, fcb, fcb,
                            out, out, ODIM, NN, ODIM, D2);
    }
}

// round 8
// speedup vs baseline: 1.0652x; 1.0652x over previous
#include <cuda_runtime.h>
#include <cstdint>
#include <math.h>

#define NN    10000
#define IND   512
#define D1    512      // HEADS*HID
#define HEADS 8
#define HID   64
#define D2    64
#define ODIM  5000
#define NE    160000
#define ET    170000   // NE + NN self loops
#define NEG   0.2f

// ---------------- scratch (static device globals; no allocation) ------------
__device__ float    g_xl1[(size_t)NN * D1];
__device__ float    g_xr1[(size_t)NN * D1];
__device__ float    g_h1 [(size_t)NN * D1];
__device__ float    g_xl2[(size_t)NN * D2];
__device__ float    g_xr2[(size_t)NN * D2];
__device__ float    g_h2 [(size_t)NN * D2];
__device__ int      g_deg[NN];
__device__ int      g_off[NN + 1];
__device__ int      g_cur[NN];
__device__ int      g_perm[ET];
__device__ int      g_is64;

// ---------------- helpers ---------------------------------------------------
__device__ __forceinline__ int eidx(const void* ei, int i) {
    return g_is64 ? (int)((const long long*)ei)[i] : ((const int*)ei)[i];
}
__device__ __forceinline__ int esrc(const void* ei, int w) {
    return (w < NE) ? eidx(ei, w) : (w - NE);
}
__device__ __forceinline__ int edst(const void* ei, int w) {
    return (w < NE) ? eidx(ei, NE + w) : (w - NE);
}
__device__ __forceinline__ float lrelu(float v) { return v > 0.f ? v : NEG * v; }
__device__ __forceinline__ uint32_t f2tf32(float f) {
    uint32_t r; asm("cvt.rna.tf32.f32 %0, %1;" : "=r"(r) : "f"(f)); return r;
}

// ---------------- tf32 mma.sync GEMM (software pipelined) --------------------
#define BKC 32
#define STR 36

__device__ __forceinline__ void mma16n8k8(float* c, const uint32_t* a, const uint32_t* b) {
    asm volatile("mma.sync.aligned.m16n8k8.row.col.f32.tf32.tf32.f32 "
        "{%0,%1,%2,%3}, {%4,%5,%6,%7}, {%8,%9}, {%0,%1,%2,%3};"
        : "+f"(c[0]), "+f"(c[1]), "+f"(c[2]), "+f"(c[3])
        : "r"(a[0]), "r"(a[1]), "r"(a[2]), "r"(a[3]), "r"(b[0]), "r"(b[1]));
}

__global__ __launch_bounds__(256) void tc_gemm(
    const float* __restrict__ A,
    const float* __restrict__ Wa, const float* __restrict__ Wb,
    const float* __restrict__ ba, const float* __restrict__ bb,
    float* __restrict__ Ca, float* __restrict__ Cb,
    int split, int M, int Nc, int K)
{
    __shared__ uint32_t As[128 * STR];
    __shared__ uint32_t Bs[128 * STR];

    int tid = threadIdx.x, wid = tid >> 5, lane = tid & 31;
    int g = lane >> 2, q = lane & 3;
    int wm = wid >> 2, wn = wid & 3;
    int rowBase = blockIdx.y * 128, colBase = blockIdx.x * 128;

    int srow = tid >> 1;
    int scol = (tid & 1) * 16;
    int garow = rowBase + srow;
    int gbrow = colBase + srow;
    const float* agp = (garow < M) ? A + (size_t)garow * K + scol : nullptr;
    const float* bgp = nullptr;
    if (gbrow < Nc)
        bgp = (gbrow < split) ? Wa + (size_t)gbrow * K + scol
                              : Wb + (size_t)(gbrow - split) * K + scol;

    float acc[4][4][4];
    #pragma unroll
    for (int i = 0; i < 4; i++)
        #pragma unroll
        for (int j = 0; j < 4; j++)
            #pragma unroll
            for (int r = 0; r < 4; r++) acc[i][j][r] = 0.f;

    int ncK = K / BKC;
    float4 ra[4], rb[4];
    #pragma unroll
    for (int j = 0; j < 4; j++) {
        ra[j] = agp ? *(const float4*)(agp + j * 4) : make_float4(0.f, 0.f, 0.f, 0.f);
        rb[j] = bgp ? *(const float4*)(bgp + j * 4) : make_float4(0.f, 0.f, 0.f, 0.f);
    }

    for (int c = 0; c < ncK; c++) {
        #pragma unroll
        for (int j = 0; j < 4; j++) {
            uint32_t* ad = &As[srow * STR + scol + j * 4];
            uint32_t* bd = &Bs[srow * STR + scol + j * 4];
            ad[0] = f2tf32(ra[j].x); ad[1] = f2tf32(ra[j].y);
            ad[2] = f2tf32(ra[j].z); ad[3] = f2tf32(ra[j].w);
            bd[0] = f2tf32(rb[j].x); bd[1] = f2tf32(rb[j].y);
            bd[2] = f2tf32(rb[j].z); bd[3] = f2tf32(rb[j].w);
        }
        __syncthreads();

        if (c + 1 < ncK) {
            int k0 = (c + 1) * BKC;
            #pragma unroll
            for (int j = 0; j < 4; j++) {
                ra[j] = agp ? *(const float4*)(agp + k0 + j * 4)
                            : make_float4(0.f, 0.f, 0.f, 0.f);
                rb[j] = bgp ? *(const float4*)(bgp + k0 + j * 4)
                            : make_float4(0.f, 0.f, 0.f, 0.f);
            }
        }

        #pragma unroll
        for (int kk = 0; kk < BKC; kk += 8) {
            uint32_t afr[4][4], bfr[4][2];
            #pragma unroll
            for (int i = 0; i < 4; i++) {
                int r = wm * 64 + i * 16 + g;
                afr[i][0] = As[(r    ) * STR + kk + q    ];
                afr[i][1] = As[(r + 8) * STR + kk + q    ];
                afr[i][2] = As[(r    ) * STR + kk + q + 4];
                afr[i][3] = As[(r + 8) * STR + kk + q + 4];
            }
            #pragma unroll
            for (int j = 0; j < 4; j++) {
                int n = wn * 32 + j * 8 + g;
                bfr[j][0] = Bs[n * STR + kk + q    ];
                bfr[j][1] = Bs[n * STR + kk + q + 4];
            }
            #pragma unroll
            for (int i = 0; i < 4; i++)
                #pragma unroll
                for (int j = 0; j < 4; j++)
                    mma16n8k8(acc[i][j], afr[i], bfr[j]);
        }
        __syncthreads();
    }

    #pragma unroll
    for (int i = 0; i < 4; i++) {
        int r0 = rowBase + wm * 64 + i * 16 + g;
        #pragma unroll
        for (int j = 0; j < 4; j++) {
            int c = colBase + wn * 32 + j * 8 + q * 2;
            if (c >= Nc) continue;
            float bv0, bv1;
            float* dst0; float* dst1;
            if (c < split) {
                bv0 = ba[c]; bv1 = ba[c + 1];
                dst0 = Ca + (size_t)r0 * split + c;
                dst1 = Ca + (size_t)(r0 + 8) * split + c;
            } else {
                int cc = c - split; int w2 = Nc - split;
                bv0 = bb[cc]; bv1 = bb[cc + 1];
                dst0 = Cb + (size_t)r0 * w2 + cc;
                dst1 = Cb + (size_t)(r0 + 8) * w2 + cc;
            }
            if (r0 < M)
                *(float2*)dst0 = make_float2(acc[i][j][0] + bv0, acc[i][j][1] + bv1);
            if (r0 + 8 < M)
                *(float2*)dst1 = make_float2(acc[i][j][2] + bv0, acc[i][j][3] + bv1);
        }
    }
}

// ---------------- init (+ int64/int32 edge-index detection) -----------------
__global__ void init_kernel(const void* ei) {
    int i = blockIdx.x * blockDim.x + threadIdx.x;
    if (i < NN) g_deg[i] = 0;
    if (i == 0) {
        g_off[NN] = ET;
        const long long* p = (const long long*)ei;
        int ok = 1;
        for (int k = 0; k < 64; k++) {
            long long v = p[k];
            if (v < 0 || v >= NN) { ok = 0; break; }
        }
        g_is64 = ok;
    }
}

// ---------------- CSR build -------------------------------------------------
__global__ void deg_kernel(const void* ei) {
    int w = blockIdx.x * blockDim.x + threadIdx.x;
    if (w >= ET) return;
    atomicAdd(&g_deg[edst(ei, w)], 1);
}

// hierarchical scan: 10 elems/thread, warp shfl scan, 32-partial scan
__global__ __launch_bounds__(1024) void scan_kernel() {
    __shared__ int wsum[32];
    int t = threadIdx.x, lane = t & 31, wid = t >> 5;
    const int CH = 10;                       // 1024*10 >= NN
    int base = t * CH;
    int loc[CH];
    int s = 0;
    #pragma unroll
    for (int k = 0; k < CH; k++) {
        int i = base + k;
        int v = (i < NN) ? g_deg[i] : 0;
        loc[k] = s;
        s += v;
    }
    int inc = s;
    #pragma unroll
    for (int o = 1; o < 32; o <<= 1) {
        int n = __shfl_up_sync(0xffffffffu, inc, o);
        if (lane >= o) inc += n;
    }
    if (lane == 31) wsum[wid] = inc;
    __syncthreads();
    if (wid == 0) {
        int w = wsum[lane];
        #pragma unroll
        for (int o = 1; o < 32; o <<= 1) {
            int n = __shfl_up_sync(0xffffffffu, w, o);
            if (lane >= o) w += n;
        }
        wsum[lane] = w;
    }
    __syncthreads();
    int thbase = inc - s + (wid ? wsum[wid - 1] : 0);
    #pragma unroll
    for (int k = 0; k < CH; k++) {
        int i = base + k;
        if (i < NN) {
            int e = thbase + loc[k];
            g_off[i] = e;
            g_cur[i] = e;
        }
    }
}

__global__ void scatter_kernel(const void* ei) {
    int w = blockIdx.x * blockDim.x + threadIdx.x;
    if (w >= ET) return;
    int pos = atomicAdd(&g_cur[edst(ei, w)], 1);
    g_perm[pos] = w;
}

// ---------------- layer-1 fused score+softmax+aggregate (block per dst) -----
// 8 warps = 8 heads; lane owns channels c0 = wid*64+lane and c1 = c0+32.
// Online softmax; each xl[src] row slice read exactly once per warp.
__global__ __launch_bounds__(256) void gat1_fused(const void* ei,
                                                  const float* __restrict__ att,
                                                  const float* __restrict__ bias)
{
    int d = blockIdx.x;
    int t = threadIdx.x, wid = t >> 5, lane = t & 31;
    int c0 = wid * 64 + lane, c1 = c0 + 32;

    float xr0 = g_xr1[(size_t)d * D1 + c0];
    float xr1v = g_xr1[(size_t)d * D1 + c1];
    float a0 = att[c0], a1 = att[c1];

    int beg = g_off[d], end = g_off[d + 1];
    float m = -INFINITY, ssum = 0.f, acc0 = 0.f, acc1 = 0.f;

    int s = esrc(ei, g_perm[beg]);
    float xl0 = g_xl1[(size_t)s * D1 + c0];
    float xl1v = g_xl1[(size_t)s * D1 + c1];

    for (int p = beg; p < end; p++) {
        float cx0 = xl0, cx1 = xl1v;
        if (p + 1 < end) {
            int s2 = esrc(ei, g_perm[p + 1]);
            xl0 = g_xl1[(size_t)s2 * D1 + c0];
            xl1v = g_xl1[(size_t)s2 * D1 + c1];
        }
        float v = lrelu(cx0 + xr0) * a0 + lrelu(cx1 + xr1v) * a1;
        #pragma unroll
        for (int o = 16; o; o >>= 1) v += __shfl_xor_sync(0xffffffffu, v, o);
        float nm = fmaxf(m, v);
        float scale = __expf(m - nm);
        float pw = __expf(v - nm);
        ssum = ssum * scale + pw;
        acc0 = acc0 * scale + pw * cx0;
        acc1 = acc1 * scale + pw * cx1;
        m = nm;
    }
    float inv = 1.f / ssum;
    g_h1[(size_t)d * D1 + c0] = fmaxf(acc0 * inv + bias[c0], 0.f);
    g_h1[(size_t)d * D1 + c1] = fmaxf(acc1 * inv + bias[c1], 0.f);
}

// ---------------- layer-2 fused (warp per dst, 1 head) -----------------------
__global__ __launch_bounds__(256) void gat2_fused(const void* ei,
                                                  const float* __restrict__ att,
                                                  const float* __restrict__ bias)
{
    int d = (blockIdx.x * blockDim.x + threadIdx.x) >> 5;
    if (d >= NN) return;
    int lane = threadIdx.x & 31;
    int c0 = lane, c1 = lane + 32;

    float xr0 = g_xr2[(size_t)d * D2 + c0];
    float xr1v = g_xr2[(size_t)d * D2 + c1];
    float a0 = att[c0], a1 = att[c1];

    int beg = g_off[d], end = g_off[d + 1];
    float m = -INFINITY, ssum = 0.f, acc0 = 0.f, acc1 = 0.f;

    int s = esrc(ei, g_perm[beg]);
    float xl0 = g_xl2[(size_t)s * D2 + c0];
    float xl1v = g_xl2[(size_t)s * D2 + c1];

    for (int p = beg; p < end; p++) {
        float cx0 = xl0, cx1 = xl1v;
        if (p + 1 < end) {
            int s2 = esrc(ei, g_perm[p + 1]);
            xl0 = g_xl2[(size_t)s2 * D2 + c0];
            xl1v = g_xl2[(size_t)s2 * D2 + c1];
        }
        float v = lrelu(cx0 + xr0) * a0 + lrelu(cx1 + xr1v) * a1;
        #pragma unroll
        for (int o = 16; o; o >>= 1) v += __shfl_xor_sync(0xffffffffu, v, o);
        float nm = fmaxf(m, v);
        float scale = __expf(m - nm);
        float pw = __expf(v - nm);
        ssum = ssum * scale + pw;
        acc0 = acc0 * scale + pw * cx0;
        acc1 = acc1 * scale + pw * cx1;
        m = nm;
    }
    float inv = 1.f / ssum;
    g_h2[(size_t)d * D2 + c0] = fmaxf(acc0 * inv + bias[c0], 0.f);
    g_h2[(size_t)d * D2 + c1] = fmaxf(acc1 * inv + bias[c1], 0.f);
}

// ---------------- launch ----------------------------------------------------
extern "C" void kernel_launch(void* const* d_in, const int* in_sizes, int n_in,
                              void* d_out, int out_size)
{
    const float* x    = (const float*)d_in[0];
    const void*  ei   = d_in[1];
    const float* W1l  = (const float*)d_in[2];
    const float* b1l  = (const float*)d_in[3];
    const float* W1r  = (const float*)d_in[4];
    const float* b1r  = (const float*)d_in[5];
    const float* att1 = (const float*)d_in[6];
    const float* bias1= (const float*)d_in[7];
    const float* W2l  = (const float*)d_in[8];
    const float* b2l  = (const float*)d_in[9];
    const float* W2r  = (const float*)d_in[10];
    const float* b2r  = (const float*)d_in[11];
    const float* att2 = (const float*)d_in[12];
    const float* bias2= (const float*)d_in[13];
    const float* fcw  = (const float*)d_in[14];
    const float* fcb  = (const float*)d_in[15];
    float* out = (float*)d_out;

    void *p_xl1, *p_xr1, *p_h1, *p_xl2, *p_xr2, *p_h2;
    cudaGetSymbolAddress(&p_xl1, g_xl1);
    cudaGetSymbolAddress(&p_xr1, g_xr1);
    cudaGetSymbolAddress(&p_h1,  g_h1);
    cudaGetSymbolAddress(&p_xl2, g_xl2);
    cudaGetSymbolAddress(&p_xr2, g_xr2);
    cudaGetSymbolAddress(&p_h2,  g_h2);

    init_kernel<<<(NN + 255) / 256, 256>>>(ei);

    deg_kernel<<<(ET + 255) / 256, 256>>>(ei);
    scan_kernel<<<1, 1024>>>();
    scatter_kernel<<<(ET + 255) / 256, 256>>>(ei);

    // layer-1 transform: fused [10000,512] x [1024,512]^T -> xl1 | xr1
    {
        dim3 g(1024 / 128, (NN + 127) / 128);
        tc_gemm<<<g, 256>>>(x, W1l, W1r, b1l, b1r,
                            (float*)p_xl1, (float*)p_xr1, D1, NN, 1024, IND);
    }

    gat1_fused<<<NN, 256>>>(ei, att1, bias1);

    // layer-2 transform: fused [10000,512] x [128,512]^T -> xl2 | xr2
    {
        dim3 g(1, (NN + 127) / 128);
        tc_gemm<<<g, 256>>>((const float*)p_h1, W2l, W2r, b2l, b2r,
                            (float*)p_xl2, (float*)p_xr2, D2, NN, 128, D1);
    }

    gat2_fused<<<(NN * 32 + 255) / 256, 256>>>(ei, att2, bias2);

    // FC: [10000,64] x [5000,64]^T -> out
    {
        dim3 g((ODIM + 127) / 128, (NN + 127) / 128);
        tc_gemm<<<g, 256>>>((const float*)p_h2, fcw, fcw, fcb, fcb,
                            out, out, ODIM, NN, ODIM, D2);
    }
}

// round 9
// speedup vs baseline: 1.1418x; 1.0719x over previous
#include <cuda_runtime.h>
#include <cstdint>
#include <math.h>

#define NN    10000
#define IND   512
#define D1    512      // HEADS*HID
#define HEADS 8
#define HID   64
#define D2    64
#define ODIM  5000
#define NE    160000
#define ET    170000   // NE + NN self loops
#define NEG   0.2f

// ---------------- scratch (static device globals; no allocation) ------------
__device__ float    g_xl1[(size_t)NN * D1];
__device__ float    g_xr1[(size_t)NN * D1];
__device__ float    g_h1 [(size_t)NN * D1];
__device__ float    g_xl2[(size_t)NN * D2];
__device__ float    g_xr2[(size_t)NN * D2];
__device__ float    g_h2 [(size_t)NN * D2];
__device__ int      g_deg[NN];
__device__ int      g_off[NN + 1];
__device__ int      g_cur[NN];
__device__ int      g_perm[ET];
__device__ int      g_is64;

// ---------------- helpers ---------------------------------------------------
__device__ __forceinline__ int eidx(const void* ei, int i) {
    return g_is64 ? (int)((const long long*)ei)[i] : ((const int*)ei)[i];
}
__device__ __forceinline__ int esrc(const void* ei, int w) {
    return (w < NE) ? eidx(ei, w) : (w - NE);
}
__device__ __forceinline__ int edst(const void* ei, int w) {
    return (w < NE) ? eidx(ei, NE + w) : (w - NE);
}
__device__ __forceinline__ float lrelu(float v) { return v > 0.f ? v : NEG * v; }
__device__ __forceinline__ uint32_t f2tf32(float f) {
    uint32_t r; asm("cvt.rna.tf32.f32 %0, %1;" : "=r"(r) : "f"(f)); return r;
}

// ---------------- tf32 mma.sync GEMM (round-4 proven form) -------------------
#define BK 32
#define STR 36

__device__ __forceinline__ void mma16n8k8(float* c, const uint32_t* a, const uint32_t* b) {
    asm volatile("mma.sync.aligned.m16n8k8.row.col.f32.tf32.tf32.f32 "
        "{%0,%1,%2,%3}, {%4,%5,%6,%7}, {%8,%9}, {%0,%1,%2,%3};"
        : "+f"(c[0]), "+f"(c[1]), "+f"(c[2]), "+f"(c[3])
        : "r"(a[0]), "r"(a[1]), "r"(a[2]), "r"(a[3]), "r"(b[0]), "r"(b[1]));
}

__global__ __launch_bounds__(256) void tc_gemm(
    const float* __restrict__ A,
    const float* __restrict__ Wa, const float* __restrict__ Wb,
    const float* __restrict__ ba, const float* __restrict__ bb,
    float* __restrict__ Ca, float* __restrict__ Cb,
    int split, int M, int Nc, int K)
{
    __shared__ uint32_t As[128 * STR];
    __shared__ uint32_t Bs[128 * STR];

    int tid = threadIdx.x, wid = tid >> 5, lane = tid & 31;
    int g = lane >> 2, q = lane & 3;
    int wm = wid >> 2, wn = wid & 3;
    int rowBase = blockIdx.y * 128, colBase = blockIdx.x * 128;

    int srow = tid >> 1;
    int scol = (tid & 1) * 16;
    int garow = rowBase + srow;
    int gbrow = colBase + srow;
    const float* agp = (garow < M) ? A + (size_t)garow * K + scol : nullptr;
    const float* bgp = nullptr;
    if (gbrow < Nc)
        bgp = (gbrow < split) ? Wa + (size_t)gbrow * K + scol
                              : Wb + (size_t)(gbrow - split) * K + scol;

    float acc[4][4][4];
    #pragma unroll
    for (int i = 0; i < 4; i++)
        #pragma unroll
        for (int j = 0; j < 4; j++)
            #pragma unroll
            for (int r = 0; r < 4; r++) acc[i][j][r] = 0.f;

    for (int k0 = 0; k0 < K; k0 += BK) {
        #pragma unroll
        for (int j = 0; j < 4; j++) {
            float4 av = agp ? *(const float4*)(agp + k0 + j * 4)
                            : make_float4(0.f, 0.f, 0.f, 0.f);
            float4 bv = bgp ? *(const float4*)(bgp + k0 + j * 4)
                            : make_float4(0.f, 0.f, 0.f, 0.f);
            uint32_t* ad = &As[srow * STR + scol + j * 4];
            uint32_t* bd = &Bs[srow * STR + scol + j * 4];
            ad[0] = f2tf32(av.x); ad[1] = f2tf32(av.y);
            ad[2] = f2tf32(av.z); ad[3] = f2tf32(av.w);
            bd[0] = f2tf32(bv.x); bd[1] = f2tf32(bv.y);
            bd[2] = f2tf32(bv.z); bd[3] = f2tf32(bv.w);
        }
        __syncthreads();

        #pragma unroll
        for (int kk = 0; kk < BK; kk += 8) {
            uint32_t afr[4][4], bfr[4][2];
            #pragma unroll
            for (int i = 0; i < 4; i++) {
                int r = wm * 64 + i * 16 + g;
                afr[i][0] = As[(r    ) * STR + kk + q    ];
                afr[i][1] = As[(r + 8) * STR + kk + q    ];
                afr[i][2] = As[(r    ) * STR + kk + q + 4];
                afr[i][3] = As[(r + 8) * STR + kk + q + 4];
            }
            #pragma unroll
            for (int j = 0; j < 4; j++) {
                int n = wn * 32 + j * 8 + g;
                bfr[j][0] = Bs[n * STR + kk + q    ];
                bfr[j][1] = Bs[n * STR + kk + q + 4];
            }
            #pragma unroll
            for (int i = 0; i < 4; i++)
                #pragma unroll
                for (int j = 0; j < 4; j++)
                    mma16n8k8(acc[i][j], afr[i], bfr[j]);
        }
        __syncthreads();
    }

    #pragma unroll
    for (int i = 0; i < 4; i++) {
        int r0 = rowBase + wm * 64 + i * 16 + g;
        #pragma unroll
        for (int j = 0; j < 4; j++) {
            int c = colBase + wn * 32 + j * 8 + q * 2;
            if (c >= Nc) continue;
            float bv0, bv1;
            float* dst0; float* dst1;
            if (c < split) {
                bv0 = ba[c]; bv1 = ba[c + 1];
                dst0 = Ca + (size_t)r0 * split + c;
                dst1 = Ca + (size_t)(r0 + 8) * split + c;
            } else {
                int cc = c - split; int w2 = Nc - split;
                bv0 = bb[cc]; bv1 = bb[cc + 1];
                dst0 = Cb + (size_t)r0 * w2 + cc;
                dst1 = Cb + (size_t)(r0 + 8) * w2 + cc;
            }
            if (r0 < M)
                *(float2*)dst0 = make_float2(acc[i][j][0] + bv0, acc[i][j][1] + bv1);
            if (r0 + 8 < M)
                *(float2*)dst1 = make_float2(acc[i][j][2] + bv0, acc[i][j][3] + bv1);
        }
    }
}

// ---------------- init (+ int64/int32 edge-index detection) -----------------
__global__ void init_kernel(const void* ei) {
    int i = blockIdx.x * blockDim.x + threadIdx.x;
    if (i < NN) g_deg[i] = 0;
    if (i == 0) {
        g_off[NN] = ET;
        const long long* p = (const long long*)ei;
        int ok = 1;
        for (int k = 0; k < 64; k++) {
            long long v = p[k];
            if (v < 0 || v >= NN) { ok = 0; break; }
        }
        g_is64 = ok;
    }
}

// ---------------- CSR build -------------------------------------------------
__global__ void deg_kernel(const void* ei) {
    int w = blockIdx.x * blockDim.x + threadIdx.x;
    if (w >= ET) return;
    atomicAdd(&g_deg[edst(ei, w)], 1);
}

// hierarchical scan: 10 elems/thread, warp shfl scan, 32-partial scan
__global__ __launch_bounds__(1024) void scan_kernel() {
    __shared__ int wsum[32];
    int t = threadIdx.x, lane = t & 31, wid = t >> 5;
    const int CH = 10;                       // 1024*10 >= NN
    int base = t * CH;
    int loc[CH];
    int s = 0;
    #pragma unroll
    for (int k = 0; k < CH; k++) {
        int i = base + k;
        int v = (i < NN) ? g_deg[i] : 0;
        loc[k] = s;
        s += v;
    }
    int inc = s;
    #pragma unroll
    for (int o = 1; o < 32; o <<= 1) {
        int n = __shfl_up_sync(0xffffffffu, inc, o);
        if (lane >= o) inc += n;
    }
    if (lane == 31) wsum[wid] = inc;
    __syncthreads();
    if (wid == 0) {
        int w = wsum[lane];
        #pragma unroll
        for (int o = 1; o < 32; o <<= 1) {
            int n = __shfl_up_sync(0xffffffffu, w, o);
            if (lane >= o) w += n;
        }
        wsum[lane] = w;
    }
    __syncthreads();
    int thbase = inc - s + (wid ? wsum[wid - 1] : 0);
    #pragma unroll
    for (int k = 0; k < CH; k++) {
        int i = base + k;
        if (i < NN) {
            int e = thbase + loc[k];
            g_off[i] = e;
            g_cur[i] = e;
        }
    }
}

__global__ void scatter_kernel(const void* ei) {
    int w = blockIdx.x * blockDim.x + threadIdx.x;
    if (w >= ET) return;
    int pos = atomicAdd(&g_cur[edst(ei, w)], 1);
    g_perm[pos] = w;
}

// ---------------- layer-1 fused score+softmax+aggregate (block per dst) -----
// 8 warps = 8 heads; lane owns channels c0 = wid*64+lane and c1 = c0+32.
// Online softmax; each xl[src] row slice read exactly once per warp.
__global__ __launch_bounds__(256) void gat1_fused(const void* ei,
                                                  const float* __restrict__ att,
                                                  const float* __restrict__ bias)
{
    int d = blockIdx.x;
    int t = threadIdx.x, wid = t >> 5, lane = t & 31;
    int c0 = wid * 64 + lane, c1 = c0 + 32;

    float xr0 = g_xr1[(size_t)d * D1 + c0];
    float xr1v = g_xr1[(size_t)d * D1 + c1];
    float a0 = att[c0], a1 = att[c1];

    int beg = g_off[d], end = g_off[d + 1];
    float m = -INFINITY, ssum = 0.f, acc0 = 0.f, acc1 = 0.f;

    int s = esrc(ei, g_perm[beg]);
    float xl0 = g_xl1[(size_t)s * D1 + c0];
    float xl1v = g_xl1[(size_t)s * D1 + c1];

    for (int p = beg; p < end; p++) {
        float cx0 = xl0, cx1 = xl1v;
        if (p + 1 < end) {
            int s2 = esrc(ei, g_perm[p + 1]);
            xl0 = g_xl1[(size_t)s2 * D1 + c0];
            xl1v = g_xl1[(size_t)s2 * D1 + c1];
        }
        float v = lrelu(cx0 + xr0) * a0 + lrelu(cx1 + xr1v) * a1;
        #pragma unroll
        for (int o = 16; o; o >>= 1) v += __shfl_xor_sync(0xffffffffu, v, o);
        float nm = fmaxf(m, v);
        float scale = __expf(m - nm);
        float pw = __expf(v - nm);
        ssum = ssum * scale + pw;
        acc0 = acc0 * scale + pw * cx0;
        acc1 = acc1 * scale + pw * cx1;
        m = nm;
    }
    float inv = 1.f / ssum;
    g_h1[(size_t)d * D1 + c0] = fmaxf(acc0 * inv + bias[c0], 0.f);
    g_h1[(size_t)d * D1 + c1] = fmaxf(acc1 * inv + bias[c1], 0.f);
}

// ---------------- layer-2 fused (warp per dst, 1 head) -----------------------
__global__ __launch_bounds__(256) void gat2_fused(const void* ei,
                                                  const float* __restrict__ att,
                                                  const float* __restrict__ bias)
{
    int d = (blockIdx.x * blockDim.x + threadIdx.x) >> 5;
    if (d >= NN) return;
    int lane = threadIdx.x & 31;
    int c0 = lane, c1 = lane + 32;

    float xr0 = g_xr2[(size_t)d * D2 + c0];
    float xr1v = g_xr2[(size_t)d * D2 + c1];
    float a0 = att[c0], a1 = att[c1];

    int beg = g_off[d], end = g_off[d + 1];
    float m = -INFINITY, ssum = 0.f, acc0 = 0.f, acc1 = 0.f;

    int s = esrc(ei, g_perm[beg]);
    float xl0 = g_xl2[(size_t)s * D2 + c0];
    float xl1v = g_xl2[(size_t)s * D2 + c1];

    for (int p = beg; p < end; p++) {
        float cx0 = xl0, cx1 = xl1v;
        if (p + 1 < end) {
            int s2 = esrc(ei, g_perm[p + 1]);
            xl0 = g_xl2[(size_t)s2 * D2 + c0];
            xl1v = g_xl2[(size_t)s2 * D2 + c1];
        }
        float v = lrelu(cx0 + xr0) * a0 + lrelu(cx1 + xr1v) * a1;
        #pragma unroll
        for (int o = 16; o; o >>= 1) v += __shfl_xor_sync(0xffffffffu, v, o);
        float nm = fmaxf(m, v);
        float scale = __expf(m - nm);
        float pw = __expf(v - nm);
        ssum = ssum * scale + pw;
        acc0 = acc0 * scale + pw * cx0;
        acc1 = acc1 * scale + pw * cx1;
        m = nm;
    }
    float inv = 1.f / ssum;
    g_h2[(size_t)d * D2 + c0] = fmaxf(acc0 * inv + bias[c0], 0.f);
    g_h2[(size_t)d * D2 + c1] = fmaxf(acc1 * inv + bias[c1], 0.f);
}

// ---------------- launch ----------------------------------------------------
extern "C" void kernel_launch(void* const* d_in, const int* in_sizes, int n_in,
                              void* d_out, int out_size)
{
    const float* x    = (const float*)d_in[0];
    const void*  ei   = d_in[1];
    const float* W1l  = (const float*)d_in[2];
    const float* b1l  = (const float*)d_in[3];
    const float* W1r  = (const float*)d_in[4];
    const float* b1r  = (const float*)d_in[5];
    const float* att1 = (const float*)d_in[6];
    const float* bias1= (const float*)d_in[7];
    const float* W2l  = (const float*)d_in[8];
    const float* b2l  = (const float*)d_in[9];
    const float* W2r  = (const float*)d_in[10];
    const float* b2r  = (const float*)d_in[11];
    const float* att2 = (const float*)d_in[12];
    const float* bias2= (const float*)d_in[13];
    const float* fcw  = (const float*)d_in[14];
    const float* fcb  = (const float*)d_in[15];
    float* out = (float*)d_out;

    void *p_xl1, *p_xr1, *p_h1, *p_xl2, *p_xr2, *p_h2;
    cudaGetSymbolAddress(&p_xl1, g_xl1);
    cudaGetSymbolAddress(&p_xr1, g_xr1);
    cudaGetSymbolAddress(&p_h1,  g_h1);
    cudaGetSymbolAddress(&p_xl2, g_xl2);
    cudaGetSymbolAddress(&p_xr2, g_xr2);
    cudaGetSymbolAddress(&p_h2,  g_h2);

    init_kernel<<<(NN + 255) / 256, 256>>>(ei);

    deg_kernel<<<(ET + 255) / 256, 256>>>(ei);
    scan_kernel<<<1, 1024>>>();
    scatter_kernel<<<(ET + 255) / 256, 256>>>(ei);

    // layer-1 transform: fused [10000,512] x [1024,512]^T -> xl1 | xr1
    {
        dim3 g(1024 / 128, (NN + 127) / 128);
        tc_gemm<<<g, 256>>>(x, W1l, W1r, b1l, b1r,
                            (float*)p_xl1, (float*)p_xr1, D1, NN, 1024, IND);
    }

    gat1_fused<<<NN, 256>>>(ei, att1, bias1);

    // layer-2 transform: fused [10000,512] x [128,512]^T -> xl2 | xr2
    {
        dim3 g(1, (NN + 127) / 128);
        tc_gemm<<<g, 256>>>((const float*)p_h1, W2l, W2r, b2l, b2r,
                            (float*)p_xl2, (float*)p_xr2, D2, NN, 128, D1);
    }

    gat2_fused<<<(NN * 32 + 255) / 256, 256>>>(ei, att2, bias2);

    // FC: [10000,64] x [5000,64]^T -> out
    {
        dim3 g((ODIM + 127) / 128, (NN + 127) / 128);
        tc_gemm<<<g, 256>>>((const float*)p_h2, fcw, fcw, fcb, fcb,
                            out, out, ODIM, NN, ODIM, D2);
    }
}

// round 10
// speedup vs baseline: 1.2094x; 1.0592x over previous
#include <cuda_runtime.h>
#include <cuda_fp16.h>
#include <cstdint>
#include <math.h>

#define NN    10000
#define IND   512
#define D1    512      // HEADS*HID
#define HEADS 8
#define HID   64
#define D2    64
#define ODIM  5000
#define NE    160000
#define ET    170000   // NE + NN self loops
#define NEG   0.2f

// ---------------- scratch (static device globals; no allocation) ------------
__device__ float    g_xl1[(size_t)NN * D1];
__device__ float    g_xr1[(size_t)NN * D1];
__device__ float    g_h1 [(size_t)NN * D1];
__device__ float    g_xl2[(size_t)NN * D2];
__device__ float    g_xr2[(size_t)NN * D2];
__device__ float    g_h2 [(size_t)NN * D2];
__device__ int      g_deg[NN];
__device__ int      g_off[NN + 1];
__device__ int      g_cur[NN];
__device__ int      g_perm[ET];
__device__ int      g_is64;

// ---------------- helpers ---------------------------------------------------
__device__ __forceinline__ int eidx(const void* ei, int i) {
    return g_is64 ? (int)((const long long*)ei)[i] : ((const int*)ei)[i];
}
__device__ __forceinline__ int esrc(const void* ei, int w) {
    return (w < NE) ? eidx(ei, w) : (w - NE);
}
__device__ __forceinline__ int edst(const void* ei, int w) {
    return (w < NE) ? eidx(ei, NE + w) : (w - NE);
}
__device__ __forceinline__ float lrelu(float v) { return v > 0.f ? v : NEG * v; }
__device__ __forceinline__ uint32_t f2h2(float a, float b) {
    __half2 h = __floats2half2_rn(a, b);
    return *(uint32_t*)&h;
}

// ---------------- fp16 mma.sync GEMM (m16n8k16, fp32 accumulate) -------------
// C[M,Nc] = A[M,K] @ W[Nc,K]^T + bias ; split into (Wa,ba,Ca | Wb,bb,Cb).
// Tile 128x128, BK=32 (halves), 8 warps of 64x32 warp tiles. K % 32 == 0.
// smem: rows of 32 halves (16 words) in 36-word stride -> fragment loads hit
// bank (4*row + q) % 32: conflict-free.
#define BK 32
#define STR 36

__device__ __forceinline__ void mma16n8k16(float* c, const uint32_t* a, const uint32_t* b) {
    asm volatile("mma.sync.aligned.m16n8k16.row.col.f32.f16.f16.f32 "
        "{%0,%1,%2,%3}, {%4,%5,%6,%7}, {%8,%9}, {%0,%1,%2,%3};"
        : "+f"(c[0]), "+f"(c[1]), "+f"(c[2]), "+f"(c[3])
        : "r"(a[0]), "r"(a[1]), "r"(a[2]), "r"(a[3]), "r"(b[0]), "r"(b[1]));
}

__global__ __launch_bounds__(256) void tc_gemm(
    const float* __restrict__ A,
    const float* __restrict__ Wa, const float* __restrict__ Wb,
    const float* __restrict__ ba, const float* __restrict__ bb,
    float* __restrict__ Ca, float* __restrict__ Cb,
    int split, int M, int Nc, int K)
{
    __shared__ uint32_t As[128 * STR];
    __shared__ uint32_t Bs[128 * STR];

    int tid = threadIdx.x, wid = tid >> 5, lane = tid & 31;
    int g = lane >> 2, q = lane & 3;
    int wm = wid >> 2, wn = wid & 3;
    int rowBase = blockIdx.y * 128, colBase = blockIdx.x * 128;

    int srow = tid >> 1;                 // 0..127
    int scol = (tid & 1) * 16;           // float (=half) index within 32-chunk
    int sword = (tid & 1) * 8;           // word index within 16-word row
    int garow = rowBase + srow;
    int gbrow = colBase + srow;
    const float* agp = (garow < M) ? A + (size_t)garow * K + scol : nullptr;
    const float* bgp = nullptr;
    if (gbrow < Nc)
        bgp = (gbrow < split) ? Wa + (size_t)gbrow * K + scol
                              : Wb + (size_t)(gbrow - split) * K + scol;

    float acc[4][4][4];
    #pragma unroll
    for (int i = 0; i < 4; i++)
        #pragma unroll
        for (int j = 0; j < 4; j++)
            #pragma unroll
            for (int r = 0; r < 4; r++) acc[i][j][r] = 0.f;

    for (int k0 = 0; k0 < K; k0 += BK) {
        // stage 32-half chunk: fp32 global -> half2 words in smem
        #pragma unroll
        for (int j = 0; j < 4; j++) {
            float4 av = agp ? *(const float4*)(agp + k0 + j * 4)
                            : make_float4(0.f, 0.f, 0.f, 0.f);
            float4 bv = bgp ? *(const float4*)(bgp + k0 + j * 4)
                            : make_float4(0.f, 0.f, 0.f, 0.f);
            uint32_t* ad = &As[srow * STR + sword + j * 2];
            uint32_t* bd = &Bs[srow * STR + sword + j * 2];
            ad[0] = f2h2(av.x, av.y); ad[1] = f2h2(av.z, av.w);
            bd[0] = f2h2(bv.x, bv.y); bd[1] = f2h2(bv.z, bv.w);
        }
        __syncthreads();

        #pragma unroll
        for (int kk = 0; kk < BK; kk += 16) {
            int kw = kk >> 1;            // word offset of this k16 step
            uint32_t afr[4][4], bfr[4][2];
            #pragma unroll
            for (int i = 0; i < 4; i++) {
                int r = wm * 64 + i * 16 + g;
                afr[i][0] = As[(r    ) * STR + kw + q    ];
                afr[i][1] = As[(r + 8) * STR + kw + q    ];
                afr[i][2] = As[(r    ) * STR + kw + q + 4];
                afr[i][3] = As[(r + 8) * STR + kw + q + 4];
            }
            #pragma unroll
            for (int j = 0; j < 4; j++) {
                int n = wn * 32 + j * 8 + g;
                bfr[j][0] = Bs[n * STR + kw + q    ];
                bfr[j][1] = Bs[n * STR + kw + q + 4];
            }
            #pragma unroll
            for (int i = 0; i < 4; i++)
                #pragma unroll
                for (int j = 0; j < 4; j++)
                    mma16n8k16(acc[i][j], afr[i], bfr[j]);
        }
        __syncthreads();
    }

    #pragma unroll
    for (int i = 0; i < 4; i++) {
        int r0 = rowBase + wm * 64 + i * 16 + g;
        #pragma unroll
        for (int j = 0; j < 4; j++) {
            int c = colBase + wn * 32 + j * 8 + q * 2;
            if (c >= Nc) continue;
            float bv0, bv1;
            float* dst0; float* dst1;
            if (c < split) {
                bv0 = ba[c]; bv1 = ba[c + 1];
                dst0 = Ca + (size_t)r0 * split + c;
                dst1 = Ca + (size_t)(r0 + 8) * split + c;
            } else {
                int cc = c - split; int w2 = Nc - split;
                bv0 = bb[cc]; bv1 = bb[cc + 1];
                dst0 = Cb + (size_t)r0 * w2 + cc;
                dst1 = Cb + (size_t)(r0 + 8) * w2 + cc;
            }
            if (r0 < M)
                *(float2*)dst0 = make_float2(acc[i][j][0] + bv0, acc[i][j][1] + bv1);
            if (r0 + 8 < M)
                *(float2*)dst1 = make_float2(acc[i][j][2] + bv0, acc[i][j][3] + bv1);
        }
    }
}

// ---------------- init (+ int64/int32 edge-index detection) -----------------
__global__ void init_kernel(const void* ei) {
    int i = blockIdx.x * blockDim.x + threadIdx.x;
    if (i < NN) g_deg[i] = 0;
    if (i == 0) {
        g_off[NN] = ET;
        const long long* p = (const long long*)ei;
        int ok = 1;
        for (int k = 0; k < 64; k++) {
            long long v = p[k];
            if (v < 0 || v >= NN) { ok = 0; break; }
        }
        g_is64 = ok;
    }
}

// ---------------- CSR build -------------------------------------------------
__global__ void deg_kernel(const void* ei) {
    int w = blockIdx.x * blockDim.x + threadIdx.x;
    if (w >= ET) return;
    atomicAdd(&g_deg[edst(ei, w)], 1);
}

// hierarchical scan: 10 elems/thread, warp shfl scan, 32-partial scan
__global__ __launch_bounds__(1024) void scan_kernel() {
    __shared__ int wsum[32];
    int t = threadIdx.x, lane = t & 31, wid = t >> 5;
    const int CH = 10;                       // 1024*10 >= NN
    int base = t * CH;
    int loc[CH];
    int s = 0;
    #pragma unroll
    for (int k = 0; k < CH; k++) {
        int i = base + k;
        int v = (i < NN) ? g_deg[i] : 0;
        loc[k] = s;
        s += v;
    }
    int inc = s;
    #pragma unroll
    for (int o = 1; o < 32; o <<= 1) {
        int n = __shfl_up_sync(0xffffffffu, inc, o);
        if (lane >= o) inc += n;
    }
    if (lane == 31) wsum[wid] = inc;
    __syncthreads();
    if (wid == 0) {
        int w = wsum[lane];
        #pragma unroll
        for (int o = 1; o < 32; o <<= 1) {
            int n = __shfl_up_sync(0xffffffffu, w, o);
            if (lane >= o) w += n;
        }
        wsum[lane] = w;
    }
    __syncthreads();
    int thbase = inc - s + (wid ? wsum[wid - 1] : 0);
    #pragma unroll
    for (int k = 0; k < CH; k++) {
        int i = base + k;
        if (i < NN) {
            int e = thbase + loc[k];
            g_off[i] = e;
            g_cur[i] = e;
        }
    }
}

__global__ void scatter_kernel(const void* ei) {
    int w = blockIdx.x * blockDim.x + threadIdx.x;
    if (w >= ET) return;
    int pos = atomicAdd(&g_cur[edst(ei, w)], 1);
    g_perm[pos] = w;
}

// ---------------- layer-1 fused score+softmax+aggregate (block per dst) -----
// 8 warps = 8 heads; lane owns channels c0 = wid*64+lane and c1 = c0+32.
// Online softmax; each xl[src] row slice read exactly once per warp.
__global__ __launch_bounds__(256) void gat1_fused(const void* ei,
                                                  const float* __restrict__ att,
                                                  const float* __restrict__ bias)
{
    int d = blockIdx.x;
    int t = threadIdx.x, wid = t >> 5, lane = t & 31;
    int c0 = wid * 64 + lane, c1 = c0 + 32;

    float xr0 = g_xr1[(size_t)d * D1 + c0];
    float xr1v = g_xr1[(size_t)d * D1 + c1];
    float a0 = att[c0], a1 = att[c1];

    int beg = g_off[d], end = g_off[d + 1];
    float m = -INFINITY, ssum = 0.f, acc0 = 0.f, acc1 = 0.f;

    int s = esrc(ei, g_perm[beg]);
    float xl0 = g_xl1[(size_t)s * D1 + c0];
    float xl1v = g_xl1[(size_t)s * D1 + c1];

    for (int p = beg; p < end; p++) {
        float cx0 = xl0, cx1 = xl1v;
        if (p + 1 < end) {
            int s2 = esrc(ei, g_perm[p + 1]);
            xl0 = g_xl1[(size_t)s2 * D1 + c0];
            xl1v = g_xl1[(size_t)s2 * D1 + c1];
        }
        float v = lrelu(cx0 + xr0) * a0 + lrelu(cx1 + xr1v) * a1;
        #pragma unroll
        for (int o = 16; o; o >>= 1) v += __shfl_xor_sync(0xffffffffu, v, o);
        float nm = fmaxf(m, v);
        float scale = __expf(m - nm);
        float pw = __expf(v - nm);
        ssum = ssum * scale + pw;
        acc0 = acc0 * scale + pw * cx0;
        acc1 = acc1 * scale + pw * cx1;
        m = nm;
    }
    float inv = 1.f / ssum;
    g_h1[(size_t)d * D1 + c0] = fmaxf(acc0 * inv + bias[c0], 0.f);
    g_h1[(size_t)d * D1 + c1] = fmaxf(acc1 * inv + bias[c1], 0.f);
}

// ---------------- layer-2 fused (warp per dst, 1 head) -----------------------
__global__ __launch_bounds__(256) void gat2_fused(const void* ei,
                                                  const float* __restrict__ att,
                                                  const float* __restrict__ bias)
{
    int d = (blockIdx.x * blockDim.x + threadIdx.x) >> 5;
    if (d >= NN) return;
    int lane = threadIdx.x & 31;
    int c0 = lane, c1 = lane + 32;

    float xr0 = g_xr2[(size_t)d * D2 + c0];
    float xr1v = g_xr2[(size_t)d * D2 + c1];
    float a0 = att[c0], a1 = att[c1];

    int beg = g_off[d], end = g_off[d + 1];
    float m = -INFINITY, ssum = 0.f, acc0 = 0.f, acc1 = 0.f;

    int s = esrc(ei, g_perm[beg]);
    float xl0 = g_xl2[(size_t)s * D2 + c0];
    float xl1v = g_xl2[(size_t)s * D2 + c1];

    for (int p = beg; p < end; p++) {
        float cx0 = xl0, cx1 = xl1v;
        if (p + 1 < end) {
            int s2 = esrc(ei, g_perm[p + 1]);
            xl0 = g_xl2[(size_t)s2 * D2 + c0];
            xl1v = g_xl2[(size_t)s2 * D2 + c1];
        }
        float v = lrelu(cx0 + xr0) * a0 + lrelu(cx1 + xr1v) * a1;
        #pragma unroll
        for (int o = 16; o; o >>= 1) v += __shfl_xor_sync(0xffffffffu, v, o);
        float nm = fmaxf(m, v);
        float scale = __expf(m - nm);
        float pw = __expf(v - nm);
        ssum = ssum * scale + pw;
        acc0 = acc0 * scale + pw * cx0;
        acc1 = acc1 * scale + pw * cx1;
        m = nm;
    }
    float inv = 1.f / ssum;
    g_h2[(size_t)d * D2 + c0] = fmaxf(acc0 * inv + bias[c0], 0.f);
    g_h2[(size_t)d * D2 + c1] = fmaxf(acc1 * inv + bias[c1], 0.f);
}

// ---------------- launch ----------------------------------------------------
extern "C" void kernel_launch(void* const* d_in, const int* in_sizes, int n_in,
                              void* d_out, int out_size)
{
    const float* x    = (const float*)d_in[0];
    const void*  ei   = d_in[1];
    const float* W1l  = (const float*)d_in[2];
    const float* b1l  = (const float*)d_in[3];
    const float* W1r  = (const float*)d_in[4];
    const float* b1r  = (const float*)d_in[5];
    const float* att1 = (const float*)d_in[6];
    const float* bias1= (const float*)d_in[7];
    const float* W2l  = (const float*)d_in[8];
    const float* b2l  = (const float*)d_in[9];
    const float* W2r  = (const float*)d_in[10];
    const float* b2r  = (const float*)d_in[11];
    const float* att2 = (const float*)d_in[12];
    const float* bias2= (const float*)d_in[13];
    const float* fcw  = (const float*)d_in[14];
    const float* fcb  = (const float*)d_in[15];
    float* out = (float*)d_out;

    void *p_xl1, *p_xr1, *p_h1, *p_xl2, *p_xr2, *p_h2;
    cudaGetSymbolAddress(&p_xl1, g_xl1);
    cudaGetSymbolAddress(&p_xr1, g_xr1);
    cudaGetSymbolAddress(&p_h1,  g_h1);
    cudaGetSymbolAddress(&p_xl2, g_xl2);
    cudaGetSymbolAddress(&p_xr2, g_xr2);
    cudaGetSymbolAddress(&p_h2,  g_h2);

    init_kernel<<<(NN + 255) / 256, 256>>>(ei);

    deg_kernel<<<(ET + 255) / 256, 256>>>(ei);
    scan_kernel<<<1, 1024>>>();
    scatter_kernel<<<(ET + 255) / 256, 256>>>(ei);

    // layer-1 transform: fused [10000,512] x [1024,512]^T -> xl1 | xr1
    {
        dim3 g(1024 / 128, (NN + 127) / 128);
        tc_gemm<<<g, 256>>>(x, W1l, W1r, b1l, b1r,
                            (float*)p_xl1, (float*)p_xr1, D1, NN, 1024, IND);
    }

    gat1_fused<<<NN, 256>>>(ei, att1, bias1);

    // layer-2 transform: fused [10000,512] x [128,512]^T -> xl2 | xr2
    {
        dim3 g(1, (NN + 127) / 128);
        tc_gemm<<<g, 256>>>((const float*)p_h1, W2l, W2r, b2l, b2r,
                            (float*)p_xl2, (float*)p_xr2, D2, NN, 128, D1);
    }

    gat2_fused<<<(NN * 32 + 255) / 256, 256>>>(ei, att2, bias2);

    // FC: [10000,64] x [5000,64]^T -> out
    {
        dim3 g((ODIM + 127) / 128, (NN + 127) / 128);
        tc_gemm<<<g, 256>>>((const float*)p_h2, fcw, fcw, fcb, fcb,
                            out, out, ODIM, NN, ODIM, D2);
    }
}